// round 14
// baseline (speedup 1.0000x reference)
#include <cuda_runtime.h>
#include <cuda_bf16.h>
#include <cuda_fp16.h>
#include <cstdint>

#define HW 327680          // 512*640 per image
#define KTOT 20480
#define KSTG 32            // K per pipeline stage
#define SPLITK 74          // uneven: first 48 blocks get 9 chunks, rest 8

#define ST 20              // smem words per 32-k row (16 data + 4 pad)
#define WT (128 * ST)      // words per 128x32 bf16 tile = 2560
#define BUFW (4 * WT)      // Ah,Al,Bh,Bl per buffer = 10240 words
#define GEMM_SMEM (2 * BUFW * 4)   // 81920 bytes

typedef unsigned long long ull;

__device__ float g_enc[512][128];   // accumulated encoder outputs (256 KB)

__device__ __forceinline__ uint32_t cvt2bf(float hi, float lo) {   // pack -> bf16x2
    uint32_t r;
    asm("cvt.rn.bf16x2.f32 %0, %1, %2;" : "=r"(r) : "f"(hi), "f"(lo));
    return r;
}
__device__ __forceinline__ void mma16816(float* d, const uint32_t* a, const uint32_t* b) {
    asm volatile(
        "mma.sync.aligned.m16n8k16.row.col.f32.bf16.bf16.f32 "
        "{%0,%1,%2,%3}, {%4,%5,%6,%7}, {%8,%9}, {%0,%1,%2,%3};"
        : "+f"(d[0]), "+f"(d[1]), "+f"(d[2]), "+f"(d[3])
        : "r"(a[0]), "r"(a[1]), "r"(a[2]), "r"(a[3]), "r"(b[0]), "r"(b[1]));
}
__device__ __forceinline__ void mma16816h(float* d, const uint32_t* a, const uint32_t* b) {
    asm volatile(
        "mma.sync.aligned.m16n8k16.row.col.f32.f16.f16.f32 "
        "{%0,%1,%2,%3}, {%4,%5,%6,%7}, {%8,%9}, {%0,%1,%2,%3};"
        : "+f"(d[0]), "+f"(d[1]), "+f"(d[2]), "+f"(d[3])
        : "r"(a[0]), "r"(a[1]), "r"(a[2]), "r"(a[3]), "r"(b[0]), "r"(b[1]));
}
__device__ __forceinline__ float tanha(float x) {
    float r;
    asm("tanh.approx.f32 %0, %1;" : "=f"(r) : "f"(x));
    return r;
}

__global__ void zero_kernel() {
    int i = blockIdx.x * 256 + threadIdx.x;   // 64 blocks x 256 = 16384 float4
    reinterpret_cast<float4*>(g_enc)[i] = make_float4(0.f, 0.f, 0.f, 0.f);
}

// ============ Split-K bf16 3-term HMMA GEMM, atomic accumulate ============
// grid = (4 M-tiles of 128 rows, 74 K-splits), block = 256 (8 warps: 2m x 4n).
__global__ __launch_bounds__(256) void gemm_kernel(
    const float* __restrict__ f1, const float* __restrict__ f2,
    const float* __restrict__ W1, const float* __restrict__ W2)
{
    extern __shared__ __align__(16) uint32_t sm[];
    const int tid = threadIdx.x;
    const int mt = blockIdx.x;
    const int ky = blockIdx.y;
    const bool isVis = (mt == 3);
    const float* __restrict__ src = isVis ? f2 : f1;
    const float* __restrict__ Wm  = isVis ? W2 : W1;
    const int row0 = mt * 128;

    const int c0  = ky * 8 + min(ky, 48);
    const int NST = 8 + (ky < 48 ? 1 : 0);
    const int kc0 = c0 * KSTG;

    const int kp = tid & 15, rg = tid >> 4;
    const float* __restrict__ abase =
        src + (size_t)((isVis ? 0 : row0) + rg * 8) * HW;
    const int wn = tid >> 1, whalf = tid & 1;
    const float* __restrict__ wbase = Wm + (size_t)wn * KTOT + kc0;

    float a0[8], a1[8];
    float4 wv[4];

    auto loadStage = [&](int s) {
        int d0 = kc0 + s * KSTG + kp * 2;
        unsigned hh = (unsigned)d0 / 160u;
        unsigned ww = (unsigned)d0 - hh * 160u;
        size_t off = (size_t)hh * 2560u + (size_t)ww * 4u;
#pragma unroll
        for (int j = 0; j < 8; ++j) {
            const float* p = abase + (size_t)j * HW + off;
            a0[j] = __ldg(p);
            a1[j] = __ldg(p + 4);
        }
        const float* wp = wbase + s * KSTG + whalf * 16;
#pragma unroll
        for (int q = 0; q < 4; ++q)
            wv[q] = *reinterpret_cast<const float4*>(wp + q * 4);
    };

    auto storeStage = [&](int buf) {
        uint32_t* Ah = sm + (size_t)buf * BUFW;
        uint32_t* Al = Ah + WT;
        uint32_t* Bh = Ah + 2 * WT;
        uint32_t* Bl = Ah + 3 * WT;
#pragma unroll
        for (int j = 0; j < 8; ++j) {
            int r = rg * 8 + j;
            float x0 = a0[j], x1 = a1[j];
            uint32_t hp = cvt2bf(x1, x0);
            float h0 = __uint_as_float(hp << 16);
            float h1 = __uint_as_float(hp & 0xffff0000u);
            uint32_t lp = cvt2bf(x1 - h1, x0 - h0);
            Ah[r * ST + kp] = hp;
            Al[r * ST + kp] = lp;
        }
#pragma unroll
        for (int q = 0; q < 4; ++q) {
            float4 v = wv[q];
            uint32_t hp0 = cvt2bf(v.y, v.x);
            uint32_t hp1 = cvt2bf(v.w, v.z);
            float h0 = __uint_as_float(hp0 << 16);
            float h1 = __uint_as_float(hp0 & 0xffff0000u);
            float h2 = __uint_as_float(hp1 << 16);
            float h3 = __uint_as_float(hp1 & 0xffff0000u);
            uint32_t lp0 = cvt2bf(v.y - h1, v.x - h0);
            uint32_t lp1 = cvt2bf(v.w - h3, v.z - h2);
            int w0 = wn * ST + whalf * 8 + 2 * q;
            *reinterpret_cast<uint2*>(Bh + w0) = make_uint2(hp0, hp1);
            *reinterpret_cast<uint2*>(Bl + w0) = make_uint2(lp0, lp1);
        }
    };

    const int wid = tid >> 5, lane = tid & 31;
    const int wm = wid >> 2, wnw = wid & 3;
    const int l4 = lane >> 2, lm = lane & 3;

    float acc[4][4][4];
#pragma unroll
    for (int i = 0; i < 4; ++i)
#pragma unroll
        for (int j = 0; j < 4; ++j)
#pragma unroll
            for (int c = 0; c < 4; ++c) acc[i][j][c] = 0.0f;

    loadStage(0);
    storeStage(0);
    __syncthreads();

    for (int s = 0; s < NST; ++s) {
        int buf = s & 1;
        if (s + 1 < NST) loadStage(s + 1);

        const uint32_t* Ah = sm + (size_t)buf * BUFW;
        const uint32_t* Al = Ah + WT;
        const uint32_t* Bh = Ah + 2 * WT;
        const uint32_t* Bl = Ah + 3 * WT;

#pragma unroll
        for (int kb = 0; kb < 2; ++kb) {
            const int ko = kb * 8 + lm;
            uint32_t ah[4][4], al[4][4], bh[4][2], bl[4][2];
#pragma unroll
            for (int i = 0; i < 4; ++i) {
                const uint32_t* p = Ah + (wm * 64 + i * 16 + l4) * ST + ko;
                ah[i][0] = p[0]; ah[i][1] = p[8 * ST]; ah[i][2] = p[4]; ah[i][3] = p[8 * ST + 4];
                const uint32_t* q = Al + (wm * 64 + i * 16 + l4) * ST + ko;
                al[i][0] = q[0]; al[i][1] = q[8 * ST]; al[i][2] = q[4]; al[i][3] = q[8 * ST + 4];
            }
#pragma unroll
            for (int j = 0; j < 4; ++j) {
                const uint32_t* p = Bh + (wnw * 32 + j * 8 + l4) * ST + ko;
                bh[j][0] = p[0]; bh[j][1] = p[4];
                const uint32_t* q = Bl + (wnw * 32 + j * 8 + l4) * ST + ko;
                bl[j][0] = q[0]; bl[j][1] = q[4];
            }
#pragma unroll
            for (int i = 0; i < 4; ++i)
#pragma unroll
                for (int j = 0; j < 4; ++j) {
                    mma16816(acc[i][j], ah[i], bh[j]);
                    mma16816(acc[i][j], ah[i], bl[j]);
                    mma16816(acc[i][j], al[i], bh[j]);
                }
        }

        if (s + 1 < NST) storeStage(buf ^ 1);
        __syncthreads();
    }

    // epilogue: atomic-accumulate 64x32 warp tile into g_enc
#pragma unroll
    for (int i = 0; i < 4; ++i) {
        int rlo = row0 + wm * 64 + i * 16 + l4;
#pragma unroll
        for (int j = 0; j < 4; ++j) {
            int col = wnw * 32 + j * 8 + 2 * lm;
            atomicAdd(&g_enc[rlo][col],     acc[i][j][0]);
            atomicAdd(&g_enc[rlo][col + 1], acc[i][j][1]);
            atomicAdd(&g_enc[rlo + 8][col],     acc[i][j][2]);
            atomicAdd(&g_enc[rlo + 8][col + 1], acc[i][j][3]);
        }
    }
}

// ===================== attn with fp16-HMMA phase 2 =====================
// grid = 256 (b, mod), block = 256; warp owns 16 k-rows.
#define SM_ENC   0        // 384
#define SM_VIS   384      // 128
#define SM_XAV   512      // 768 (pre-scaled by 1/16)
#define SM_WH    1280     // 96
#define SM_WCE   1408     // 32 rows x 280 halves = 4480 words -> 5888
#define SM_ATT   5888     // 8 warps x 16 rows x 140 words = 17920 -> 23808
#define SM_TOTAL 23808    // words -> 95232 bytes
#define AST 280           // halves per strip row (272 data + 8 pad)
#define ASTW 140          // words per strip row

__global__ __launch_bounds__(256) void attn_kernel(
    const float* __restrict__ b1, const float* __restrict__ b2,
    const float* __restrict__ Aa, const float* __restrict__ Av,
    const float* __restrict__ Wa, const float* __restrict__ Wv,
    const float* __restrict__ Wca, const float* __restrict__ Wcv,
    const float* __restrict__ Wha, const float* __restrict__ Whv,
    float* __restrict__ out)
{
    extern __shared__ __align__(16) float fsm[];
    float* enc_a = fsm + SM_ENC;
    float* visr  = fsm + SM_VIS;
    float* XAv   = fsm + SM_XAV;
    float* Wh_s  = fsm + SM_WH;
    __half* wce  = reinterpret_cast<__half*>(fsm + SM_WCE);

    const int tid = threadIdx.x;
    const int b = blockIdx.x >> 1;
    const int mod = blockIdx.x & 1;   // 0 = audio, 1 = visual

    // load encoder rows directly (g_enc fully reduced by gemm atomics)
    if (tid < 128) {
        int rl = tid >> 5, q = tid & 31;
        int grow = (rl < 3) ? (b * 3 + rl) : (384 + b);
        float4 s4 = *reinterpret_cast<const float4*>(&g_enc[grow][q * 4]);
        if (rl < 3) {
            const float4 bb = *reinterpret_cast<const float4*>(&b1[q * 4]);
            *reinterpret_cast<float4*>(&enc_a[rl * 128 + q * 4]) =
                make_float4(s4.x + bb.x, s4.y + bb.y, s4.z + bb.z, s4.w + bb.w);
        } else {
            const float4 bb = *reinterpret_cast<const float4*>(&b2[q * 4]);
            *reinterpret_cast<float4*>(&visr[q * 4]) =
                make_float4(s4.x + bb.x, s4.y + bb.y, s4.z + bb.z, s4.w + bb.w);
        }
    }
    if (tid < 96) Wh_s[tid] = (mod ? Whv : Wha)[tid];
    // stage WcE (fp16): cols 0..255 = Wc, 256..258 = Wx, 259..271 = 0
    {
        const float* Wc = mod ? Wcv : Wca;
        for (int idx = tid; idx < 2048; idx += 256) {   // float4 granularity
            int h = idx >> 6, m4 = idx & 63;
            float4 v = *reinterpret_cast<const float4*>(Wc + h * 256 + m4 * 4);
            __half2* dst = reinterpret_cast<__half2*>(wce + h * AST + m4 * 4);
            dst[0] = __floats2half2_rn(v.x, v.y);
            dst[1] = __floats2half2_rn(v.z, v.w);
        }
        const float* Wx = mod ? Wv : Wa;
        if (tid < 96) {
            int h = tid / 3, c = tid - 3 * h;
            wce[h * AST + 256 + c] = __float2half_rn(Wx[tid]);
        }
        for (int idx = tid; idx < 32 * 13; idx += 256) {
            int h = idx / 13, c = idx - 13 * h;
            wce[h * AST + 259 + c] = __float2half_rn(0.0f);
        }
    }
    __syncthreads();

    const float* M = mod ? Av : Aa;
    {
        int m = tid;
        const float scale = 0.0625f;   // fold 1/sqrt(256) into XAv
        float av0 = (m < 128) ? enc_a[m]       : visr[m - 128];
        float av1 = (m < 128) ? enc_a[128 + m] : visr[m - 128];
        float av2 = (m < 128) ? enc_a[256 + m] : visr[m - 128];
        XAv[m]       = scale * (M[0] * av0 + M[1] * av1 + M[2] * av2);
        XAv[256 + m] = scale * (M[3] * av0 + M[4] * av1 + M[5] * av2);
        XAv[512 + m] = scale * (M[6] * av0 + M[7] * av1 + M[8] * av2);
    }
    __syncthreads();

    const int wid = tid >> 5, h = tid & 31;
    const int l4 = h >> 2, lm = h & 3;
    const int k0 = wid * 16;
    __half* strip = reinterpret_cast<__half*>(fsm + SM_ATT) + wid * 16 * AST;

    // ---- Phase 1: tanh rows (fp16) + e-columns ----
    float e0[16], e1[16], e2[16];
#pragma unroll
    for (int r = 0; r < 16; ++r) {
        int k = k0 + r;
        if (mod == 0) { e0[r] = enc_a[k]; e1[r] = enc_a[128 + k]; e2[r] = enc_a[256 + k]; }
        else          { e0[r] = visr[k];  e1[r] = e0[r];          e2[r] = e0[r]; }
    }
#pragma unroll
    for (int mc = 0; mc < 8; ++mc) {
        int m = mc * 32 + h;
        float x0 = XAv[m], x1 = XAv[256 + m], x2 = XAv[512 + m];
#pragma unroll
        for (int r = 0; r < 16; ++r) {
            float s = e0[r] * x0 + e1[r] * x1 + e2[r] * x2;
            strip[r * AST + m] = __float2half_rn(tanha(s));
        }
    }
    // e-columns 256..258 (lane h == r writes row r), zeros 259..271
#pragma unroll
    for (int r = 0; r < 16; ++r) {
        if (h == r) {
            strip[r * AST + 256] = __float2half_rn(e0[r]);
            strip[r * AST + 257] = __float2half_rn(e1[r]);
            strip[r * AST + 258] = __float2half_rn(e2[r]);
        }
    }
    for (int z = h; z < 16 * 13; z += 32) {
        int r = z / 13, c = z - 13 * r;
        strip[r * AST + 259 + c] = __float2half_rn(0.0f);
    }
    __syncwarp();

    // ---- Phase 2: H(16x32) = relu( strip(16x272) @ WcE^T(272x32) ) via fp16 HMMA
    const uint32_t* stripw = reinterpret_cast<const uint32_t*>(strip);
    const uint32_t* wcew   = reinterpret_cast<const uint32_t*>(wce);

    float acc[4][4];
#pragma unroll
    for (int j = 0; j < 4; ++j)
#pragma unroll
        for (int c = 0; c < 4; ++c) acc[j][c] = 0.0f;

#pragma unroll
    for (int t = 0; t < 17; ++t) {
        const int ko = t * 8 + lm;
        uint32_t a[4];
        const uint32_t* ap = stripw + l4 * ASTW + ko;
        a[0] = ap[0]; a[1] = ap[8 * ASTW]; a[2] = ap[4]; a[3] = ap[8 * ASTW + 4];
#pragma unroll
        for (int j = 0; j < 4; ++j) {
            const uint32_t* bp = wcew + (j * 8 + l4) * ASTW + ko;
            uint32_t bfr[2] = { bp[0], bp[4] };
            mma16816h(acc[j], a, bfr);
        }
    }

    // ---- Epilogue: relu, x Wh, reduce over h, + enc residual ----
    float r0lo = 0.f, r1lo = 0.f, r2lo = 0.f;
    float r0hi = 0.f, r1hi = 0.f, r2hi = 0.f;
#pragma unroll
    for (int j = 0; j < 4; ++j) {
        int h0 = j * 8 + 2 * lm, h1 = h0 + 1;
        float w00 = Wh_s[h0],      w01 = Wh_s[h1];
        float w10 = Wh_s[32 + h0], w11 = Wh_s[32 + h1];
        float w20 = Wh_s[64 + h0], w21 = Wh_s[64 + h1];
        float H00 = fmaxf(acc[j][0], 0.f), H01 = fmaxf(acc[j][1], 0.f);
        float H10 = fmaxf(acc[j][2], 0.f), H11 = fmaxf(acc[j][3], 0.f);
        r0lo += H00 * w00 + H01 * w01;
        r1lo += H00 * w10 + H01 * w11;
        r2lo += H00 * w20 + H01 * w21;
        r0hi += H10 * w00 + H11 * w01;
        r1hi += H10 * w10 + H11 * w11;
        r2hi += H10 * w20 + H11 * w21;
    }
#pragma unroll
    for (int o = 1; o <= 2; o <<= 1) {
        r0lo += __shfl_xor_sync(0xffffffffu, r0lo, o);
        r1lo += __shfl_xor_sync(0xffffffffu, r1lo, o);
        r2lo += __shfl_xor_sync(0xffffffffu, r2lo, o);
        r0hi += __shfl_xor_sync(0xffffffffu, r0hi, o);
        r1hi += __shfl_xor_sync(0xffffffffu, r1hi, o);
        r2hi += __shfl_xor_sync(0xffffffffu, r2hi, o);
    }
    if (lm == 0) {
        float* ob = out + (size_t)b * 768 + mod * 128;
        int klo = k0 + l4, khi = klo + 8;
        float a0, a1, a2, c0, c1, c2;
        if (mod == 0) {
            a0 = enc_a[klo]; a1 = enc_a[128 + klo]; a2 = enc_a[256 + klo];
            c0 = enc_a[khi]; c1 = enc_a[128 + khi]; c2 = enc_a[256 + khi];
        } else {
            a0 = visr[klo]; a1 = a0; a2 = a0;
            c0 = visr[khi]; c1 = c0; c2 = c0;
        }
        ob[klo]       = r0lo + a0;
        ob[256 + klo] = r1lo + a1;
        ob[512 + klo] = r2lo + a2;
        ob[khi]       = r0hi + c0;
        ob[256 + khi] = r1hi + c1;
        ob[512 + khi] = r2hi + c2;
    }
}

extern "C" void kernel_launch(void* const* d_in, const int* in_sizes, int n_in,
                              void* d_out, int out_size)
{
    const float* f1  = (const float*)d_in[0];
    const float* f2  = (const float*)d_in[1];
    const float* W1  = (const float*)d_in[2];
    const float* b1  = (const float*)d_in[3];
    const float* W2  = (const float*)d_in[4];
    const float* b2  = (const float*)d_in[5];
    const float* Aa  = (const float*)d_in[6];
    const float* Av  = (const float*)d_in[7];
    const float* Wa  = (const float*)d_in[8];
    const float* Wv  = (const float*)d_in[9];
    const float* Wca = (const float*)d_in[10];
    const float* Wcv = (const float*)d_in[11];
    const float* Wha = (const float*)d_in[12];
    const float* Whv = (const float*)d_in[13];
    float* out = (float*)d_out;

    cudaFuncSetAttribute(gemm_kernel, cudaFuncAttributeMaxDynamicSharedMemorySize,
                         GEMM_SMEM);
    cudaFuncSetAttribute(attn_kernel, cudaFuncAttributeMaxDynamicSharedMemorySize,
                         SM_TOTAL * sizeof(float));

    zero_kernel<<<64, 256>>>();
    dim3 g(4, SPLITK);
    gemm_kernel<<<g, 256, GEMM_SMEM>>>(f1, f2, W1, W2);
    attn_kernel<<<256, 256, SM_TOTAL * sizeof(float)>>>(
        b1, b2, Aa, Av, Wa, Wv, Wca, Wcv, Wha, Whv, out);
}

// round 15
// speedup vs baseline: 1.0365x; 1.0365x over previous
#include <cuda_runtime.h>
#include <cuda_bf16.h>
#include <cuda_fp16.h>
#include <cstdint>

#define HW 327680          // 512*640 per image
#define KTOT 20480
#define KSTG 32            // K per pipeline stage
#define SPLITK 74          // uneven: first 48 blocks get 9 chunks, rest 8

#define RST 40             // interleaved row stride in words (32 data, no pad; 8r mod 32 rotation)
#define TILW (128 * RST)   // words per interleaved 128x32 tile (A or B) = 5120
#define BUFW (2 * TILW)    // A + B per buffer = 10240 words
#define GEMM_SMEM (2 * BUFW * 4)   // 81920 bytes

typedef unsigned long long ull;

__device__ float g_part[SPLITK][512][128];   // split-K partials

__device__ __forceinline__ uint32_t cvt2bf(float hi, float lo) {   // pack -> bf16x2
    uint32_t r;
    asm("cvt.rn.bf16x2.f32 %0, %1, %2;" : "=r"(r) : "f"(hi), "f"(lo));
    return r;
}
__device__ __forceinline__ void mma16816(float* d, const uint32_t* a, const uint32_t* b) {
    asm volatile(
        "mma.sync.aligned.m16n8k16.row.col.f32.bf16.bf16.f32 "
        "{%0,%1,%2,%3}, {%4,%5,%6,%7}, {%8,%9}, {%0,%1,%2,%3};"
        : "+f"(d[0]), "+f"(d[1]), "+f"(d[2]), "+f"(d[3])
        : "r"(a[0]), "r"(a[1]), "r"(a[2]), "r"(a[3]), "r"(b[0]), "r"(b[1]));
}
__device__ __forceinline__ void mma16816h(float* d, const uint32_t* a, const uint32_t* b) {
    asm volatile(
        "mma.sync.aligned.m16n8k16.row.col.f32.f16.f16.f32 "
        "{%0,%1,%2,%3}, {%4,%5,%6,%7}, {%8,%9}, {%0,%1,%2,%3};"
        : "+f"(d[0]), "+f"(d[1]), "+f"(d[2]), "+f"(d[3])
        : "r"(a[0]), "r"(a[1]), "r"(a[2]), "r"(a[3]), "r"(b[0]), "r"(b[1]));
}
__device__ __forceinline__ float tanha(float x) {
    float r;
    asm("tanh.approx.f32 %0, %1;" : "=f"(r) : "f"(x));
    return r;
}

// ===== Split-K bf16 3-term HMMA GEMM, interleaved hi/lo smem tiles =====
// grid = (4 M-tiles of 128 rows, 74 K-splits), block = 256 (8 warps: 2m x 4n).
__global__ __launch_bounds__(256) void gemm_kernel(
    const float* __restrict__ f1, const float* __restrict__ f2,
    const float* __restrict__ W1, const float* __restrict__ W2)
{
    extern __shared__ __align__(16) uint32_t sm[];
    const int tid = threadIdx.x;
    const int mt = blockIdx.x;
    const int ky = blockIdx.y;
    const bool isVis = (mt == 3);
    const float* __restrict__ src = isVis ? f2 : f1;
    const float* __restrict__ Wm  = isVis ? W2 : W1;
    const int row0 = mt * 128;

    const int c0  = ky * 8 + min(ky, 48);
    const int NST = 8 + (ky < 48 ? 1 : 0);
    const int kc0 = c0 * KSTG;

    const int kp = tid & 15, rg = tid >> 4;
    const float* __restrict__ abase =
        src + (size_t)((isVis ? 0 : row0) + rg * 8) * HW;
    const int wn = tid >> 1, whalf = tid & 1;
    const float* __restrict__ wbase = Wm + (size_t)wn * KTOT + kc0;

    float a0[8], a1[8];
    float4 wv[4];

    auto loadStage = [&](int s) {
        int d0 = kc0 + s * KSTG + kp * 2;
        unsigned hh = (unsigned)d0 / 160u;
        unsigned ww = (unsigned)d0 - hh * 160u;
        size_t off = (size_t)hh * 2560u + (size_t)ww * 4u;
#pragma unroll
        for (int j = 0; j < 8; ++j) {
            const float* p = abase + (size_t)j * HW + off;
            a0[j] = __ldg(p);
            a1[j] = __ldg(p + 4);
        }
        const float* wp = wbase + s * KSTG + whalf * 16;
#pragma unroll
        for (int q = 0; q < 4; ++q)
            wv[q] = *reinterpret_cast<const float4*>(wp + q * 4);
    };

    auto storeStage = [&](int buf) {
        uint32_t* Ab = sm + (size_t)buf * BUFW;         // interleaved [hp, lp]
        uint32_t* Bb = Ab + TILW;
#pragma unroll
        for (int j = 0; j < 8; ++j) {
            int r = rg * 8 + j;
            float x0 = a0[j], x1 = a1[j];
            uint32_t hp = cvt2bf(x1, x0);
            float h0 = __uint_as_float(hp << 16);
            float h1 = __uint_as_float(hp & 0xffff0000u);
            uint32_t lp = cvt2bf(x1 - h1, x0 - h0);
            *reinterpret_cast<uint2*>(Ab + r * RST + kp * 2) = make_uint2(hp, lp);
        }
#pragma unroll
        for (int q = 0; q < 4; ++q) {
            float4 v = wv[q];
            uint32_t hp0 = cvt2bf(v.y, v.x);
            uint32_t hp1 = cvt2bf(v.w, v.z);
            float h0 = __uint_as_float(hp0 << 16);
            float h1 = __uint_as_float(hp0 & 0xffff0000u);
            float h2 = __uint_as_float(hp1 << 16);
            float h3 = __uint_as_float(hp1 & 0xffff0000u);
            uint32_t lp0 = cvt2bf(v.y - h1, v.x - h0);
            uint32_t lp1 = cvt2bf(v.w - h3, v.z - h2);
            int w0 = wn * RST + (whalf * 8 + 2 * q) * 2;
            *reinterpret_cast<uint2*>(Bb + w0)     = make_uint2(hp0, lp0);
            *reinterpret_cast<uint2*>(Bb + w0 + 2) = make_uint2(hp1, lp1);
        }
    };

    const int wid = tid >> 5, lane = tid & 31;
    const int wm = wid >> 2, wnw = wid & 3;
    const int l4 = lane >> 2, lm = lane & 3;

    float acc[4][4][4];
#pragma unroll
    for (int i = 0; i < 4; ++i)
#pragma unroll
        for (int j = 0; j < 4; ++j)
#pragma unroll
            for (int c = 0; c < 4; ++c) acc[i][j][c] = 0.0f;

    loadStage(0);
    storeStage(0);
    __syncthreads();

    for (int s = 0; s < NST; ++s) {
        int buf = s & 1;
        if (s + 1 < NST) loadStage(s + 1);

        const uint32_t* Ab = sm + (size_t)buf * BUFW;
        const uint32_t* Bb = Ab + TILW;

#pragma unroll
        for (int kb = 0; kb < 2; ++kb) {
            const int ko2 = (kb * 8 + lm) * 2;
            uint32_t ah[4][4], al[4][4], bh[4][2], bl[4][2];
#pragma unroll
            for (int i = 0; i < 4; ++i) {
                const uint32_t* p = Ab + (wm * 64 + i * 16 + l4) * RST + ko2;
                uint2 p0 = *reinterpret_cast<const uint2*>(p);
                uint2 p1 = *reinterpret_cast<const uint2*>(p + 8 * RST);
                uint2 p2 = *reinterpret_cast<const uint2*>(p + 8);
                uint2 p3 = *reinterpret_cast<const uint2*>(p + 8 * RST + 8);
                ah[i][0] = p0.x; al[i][0] = p0.y;
                ah[i][1] = p1.x; al[i][1] = p1.y;
                ah[i][2] = p2.x; al[i][2] = p2.y;
                ah[i][3] = p3.x; al[i][3] = p3.y;
            }
#pragma unroll
            for (int j = 0; j < 4; ++j) {
                const uint32_t* p = Bb + (wnw * 32 + j * 8 + l4) * RST + ko2;
                uint2 p0 = *reinterpret_cast<const uint2*>(p);
                uint2 p1 = *reinterpret_cast<const uint2*>(p + 8);
                bh[j][0] = p0.x; bl[j][0] = p0.y;
                bh[j][1] = p1.x; bl[j][1] = p1.y;
            }
#pragma unroll
            for (int i = 0; i < 4; ++i)
#pragma unroll
                for (int j = 0; j < 4; ++j) {
                    mma16816(acc[i][j], ah[i], bh[j]);
                    mma16816(acc[i][j], ah[i], bl[j]);
                    mma16816(acc[i][j], al[i], bh[j]);
                }
        }

        if (s + 1 < NST) storeStage(buf ^ 1);
        __syncthreads();
    }

    // epilogue: write 64x32 warp tile to g_part
#pragma unroll
    for (int i = 0; i < 4; ++i) {
        int rlo = row0 + wm * 64 + i * 16 + l4;
#pragma unroll
        for (int j = 0; j < 4; ++j) {
            int col = wnw * 32 + j * 8 + 2 * lm;
            *reinterpret_cast<float2*>(&g_part[blockIdx.y][rlo][col]) =
                make_float2(acc[i][j][0], acc[i][j][1]);
            *reinterpret_cast<float2*>(&g_part[blockIdx.y][rlo + 8][col]) =
                make_float2(acc[i][j][2], acc[i][j][3]);
        }
    }
}

// ===================== attn with fp16-HMMA phase 2 (R13) =====================
#define SM_ENC   0        // 384
#define SM_VIS   384      // 128
#define SM_XAV   512      // 768 (pre-scaled by 1/16)
#define SM_WH    1280     // 96
#define SM_WCE   1408     // 32 rows x 280 halves = 4480 words -> 5888
#define SM_ATT   5888     // 8 warps x 16 rows x 140 words = 17920 -> 23808
#define SM_TOTAL 23808    // words -> 95232 bytes
#define AST 280           // halves per strip row (272 data + 8 pad)
#define ASTW 140          // words per strip row

__global__ __launch_bounds__(256) void attn_kernel(
    const float* __restrict__ b1, const float* __restrict__ b2,
    const float* __restrict__ Aa, const float* __restrict__ Av,
    const float* __restrict__ Wa, const float* __restrict__ Wv,
    const float* __restrict__ Wca, const float* __restrict__ Wcv,
    const float* __restrict__ Wha, const float* __restrict__ Whv,
    float* __restrict__ out)
{
    extern __shared__ __align__(16) float fsm[];
    float* enc_a = fsm + SM_ENC;
    float* visr  = fsm + SM_VIS;
    float* XAv   = fsm + SM_XAV;
    float* Wh_s  = fsm + SM_WH;
    __half* wce  = reinterpret_cast<__half*>(fsm + SM_WCE);
    float4* red  = reinterpret_cast<float4*>(fsm + SM_ATT);   // alias before strips

    const int tid = threadIdx.x;
    const int b = blockIdx.x >> 1;
    const int mod = blockIdx.x & 1;   // 0 = audio, 1 = visual

    // split-K reduction: 4 rows x 128 cols over 74 partials
    {
        int e = tid & 127;
        int half = tid >> 7;
        int rl = e >> 5, q = e & 31;
        int grow = (rl < 3) ? (b * 3 + rl) : (384 + b);
        float4 a4 = make_float4(0.f, 0.f, 0.f, 0.f);
#pragma unroll 8
        for (int s = 0; s < 37; ++s) {
            const float4 v = *reinterpret_cast<const float4*>(
                &g_part[half * 37 + s][grow][q * 4]);
            a4.x += v.x; a4.y += v.y; a4.z += v.z; a4.w += v.w;
        }
        red[tid] = a4;
    }
    if (tid < 96) Wh_s[tid] = (mod ? Whv : Wha)[tid];
    // stage WcE (fp16): cols 0..255 = Wc, 256..258 = Wx, 259..271 = 0
    {
        const float* Wc = mod ? Wcv : Wca;
        for (int idx = tid; idx < 2048; idx += 256) {   // float4 granularity
            int h = idx >> 6, m4 = idx & 63;
            float4 v = *reinterpret_cast<const float4*>(Wc + h * 256 + m4 * 4);
            __half2* dst = reinterpret_cast<__half2*>(wce + h * AST + m4 * 4);
            dst[0] = __floats2half2_rn(v.x, v.y);
            dst[1] = __floats2half2_rn(v.z, v.w);
        }
        const float* Wx = mod ? Wv : Wa;
        if (tid < 96) {
            int h = tid / 3, c = tid - 3 * h;
            wce[h * AST + 256 + c] = __float2half_rn(Wx[tid]);
        }
        for (int idx = tid; idx < 32 * 13; idx += 256) {
            int h = idx / 13, c = idx - 13 * h;
            wce[h * AST + 259 + c] = __float2half_rn(0.0f);
        }
    }
    __syncthreads();

    if (tid < 128) {
        int rl = tid >> 5, q = tid & 31;
        float4 v0 = red[tid], v1 = red[128 + tid];
        float4 s4 = make_float4(v0.x + v1.x, v0.y + v1.y, v0.z + v1.z, v0.w + v1.w);
        if (rl < 3) {
            const float4 bb = *reinterpret_cast<const float4*>(&b1[q * 4]);
            *reinterpret_cast<float4*>(&enc_a[rl * 128 + q * 4]) =
                make_float4(s4.x + bb.x, s4.y + bb.y, s4.z + bb.z, s4.w + bb.w);
        } else {
            const float4 bb = *reinterpret_cast<const float4*>(&b2[q * 4]);
            *reinterpret_cast<float4*>(&visr[q * 4]) =
                make_float4(s4.x + bb.x, s4.y + bb.y, s4.z + bb.z, s4.w + bb.w);
        }
    }
    __syncthreads();

    const float* M = mod ? Av : Aa;
    {
        int m = tid;
        const float scale = 0.0625f;   // fold 1/sqrt(256) into XAv
        float av0 = (m < 128) ? enc_a[m]       : visr[m - 128];
        float av1 = (m < 128) ? enc_a[128 + m] : visr[m - 128];
        float av2 = (m < 128) ? enc_a[256 + m] : visr[m - 128];
        XAv[m]       = scale * (M[0] * av0 + M[1] * av1 + M[2] * av2);
        XAv[256 + m] = scale * (M[3] * av0 + M[4] * av1 + M[5] * av2);
        XAv[512 + m] = scale * (M[6] * av0 + M[7] * av1 + M[8] * av2);
    }
    __syncthreads();

    const int wid = tid >> 5, h = tid & 31;
    const int l4 = h >> 2, lm = h & 3;
    const int k0 = wid * 16;
    __half* strip = reinterpret_cast<__half*>(fsm + SM_ATT) + wid * 16 * AST;

    // ---- Phase 1: tanh rows (fp16) + e-columns ----
    float e0[16], e1[16], e2[16];
#pragma unroll
    for (int r = 0; r < 16; ++r) {
        int k = k0 + r;
        if (mod == 0) { e0[r] = enc_a[k]; e1[r] = enc_a[128 + k]; e2[r] = enc_a[256 + k]; }
        else          { e0[r] = visr[k];  e1[r] = e0[r];          e2[r] = e0[r]; }
    }
#pragma unroll
    for (int mc = 0; mc < 8; ++mc) {
        int m = mc * 32 + h;
        float x0 = XAv[m], x1 = XAv[256 + m], x2 = XAv[512 + m];
#pragma unroll
        for (int r = 0; r < 16; ++r) {
            float s = e0[r] * x0 + e1[r] * x1 + e2[r] * x2;
            strip[r * AST + m] = __float2half_rn(tanha(s));
        }
    }
    // e-columns 256..258 (lane h == r writes row r), zeros 259..271
#pragma unroll
    for (int r = 0; r < 16; ++r) {
        if (h == r) {
            strip[r * AST + 256] = __float2half_rn(e0[r]);
            strip[r * AST + 257] = __float2half_rn(e1[r]);
            strip[r * AST + 258] = __float2half_rn(e2[r]);
        }
    }
    for (int z = h; z < 16 * 13; z += 32) {
        int r = z / 13, c = z - 13 * r;
        strip[r * AST + 259 + c] = __float2half_rn(0.0f);
    }
    __syncwarp();

    // ---- Phase 2: H(16x32) = relu( strip(16x272) @ WcE^T(272x32) ) via fp16 HMMA
    const uint32_t* stripw = reinterpret_cast<const uint32_t*>(strip);
    const uint32_t* wcew   = reinterpret_cast<const uint32_t*>(wce);

    float acc[4][4];
#pragma unroll
    for (int j = 0; j < 4; ++j)
#pragma unroll
        for (int c = 0; c < 4; ++c) acc[j][c] = 0.0f;

#pragma unroll
    for (int t = 0; t < 17; ++t) {
        const int ko = t * 8 + lm;
        uint32_t a[4];
        const uint32_t* ap = stripw + l4 * ASTW + ko;
        a[0] = ap[0]; a[1] = ap[8 * ASTW]; a[2] = ap[4]; a[3] = ap[8 * ASTW + 4];
#pragma unroll
        for (int j = 0; j < 4; ++j) {
            const uint32_t* bp = wcew + (j * 8 + l4) * ASTW + ko;
            uint32_t bfr[2] = { bp[0], bp[4] };
            mma16816h(acc[j], a, bfr);
        }
    }

    // ---- Epilogue: relu, x Wh, reduce over h, + enc residual ----
    float r0lo = 0.f, r1lo = 0.f, r2lo = 0.f;
    float r0hi = 0.f, r1hi = 0.f, r2hi = 0.f;
#pragma unroll
    for (int j = 0; j < 4; ++j) {
        int h0 = j * 8 + 2 * lm, h1 = h0 + 1;
        float w00 = Wh_s[h0],      w01 = Wh_s[h1];
        float w10 = Wh_s[32 + h0], w11 = Wh_s[32 + h1];
        float w20 = Wh_s[64 + h0], w21 = Wh_s[64 + h1];
        float H00 = fmaxf(acc[j][0], 0.f), H01 = fmaxf(acc[j][1], 0.f);
        float H10 = fmaxf(acc[j][2], 0.f), H11 = fmaxf(acc[j][3], 0.f);
        r0lo += H00 * w00 + H01 * w01;
        r1lo += H00 * w10 + H01 * w11;
        r2lo += H00 * w20 + H01 * w21;
        r0hi += H10 * w00 + H11 * w01;
        r1hi += H10 * w10 + H11 * w11;
        r2hi += H10 * w20 + H11 * w21;
    }
#pragma unroll
    for (int o = 1; o <= 2; o <<= 1) {
        r0lo += __shfl_xor_sync(0xffffffffu, r0lo, o);
        r1lo += __shfl_xor_sync(0xffffffffu, r1lo, o);
        r2lo += __shfl_xor_sync(0xffffffffu, r2lo, o);
        r0hi += __shfl_xor_sync(0xffffffffu, r0hi, o);
        r1hi += __shfl_xor_sync(0xffffffffu, r1hi, o);
        r2hi += __shfl_xor_sync(0xffffffffu, r2hi, o);
    }
    if (lm == 0) {
        float* ob = out + (size_t)b * 768 + mod * 128;
        int klo = k0 + l4, khi = klo + 8;
        float a0, a1, a2, c0, c1, c2;
        if (mod == 0) {
            a0 = enc_a[klo]; a1 = enc_a[128 + klo]; a2 = enc_a[256 + klo];
            c0 = enc_a[khi]; c1 = enc_a[128 + khi]; c2 = enc_a[256 + khi];
        } else {
            a0 = visr[klo]; a1 = a0; a2 = a0;
            c0 = visr[khi]; c1 = c0; c2 = c0;
        }
        ob[klo]       = r0lo + a0;
        ob[256 + klo] = r1lo + a1;
        ob[512 + klo] = r2lo + a2;
        ob[khi]       = r0hi + c0;
        ob[256 + khi] = r1hi + c1;
        ob[512 + khi] = r2hi + c2;
    }
}

extern "C" void kernel_launch(void* const* d_in, const int* in_sizes, int n_in,
                              void* d_out, int out_size)
{
    const float* f1  = (const float*)d_in[0];
    const float* f2  = (const float*)d_in[1];
    const float* W1  = (const float*)d_in[2];
    const float* b1  = (const float*)d_in[3];
    const float* W2  = (const float*)d_in[4];
    const float* b2  = (const float*)d_in[5];
    const float* Aa  = (const float*)d_in[6];
    const float* Av  = (const float*)d_in[7];
    const float* Wa  = (const float*)d_in[8];
    const float* Wv  = (const float*)d_in[9];
    const float* Wca = (const float*)d_in[10];
    const float* Wcv = (const float*)d_in[11];
    const float* Wha = (const float*)d_in[12];
    const float* Whv = (const float*)d_in[13];
    float* out = (float*)d_out;

    cudaFuncSetAttribute(gemm_kernel, cudaFuncAttributeMaxDynamicSharedMemorySize,
                         GEMM_SMEM);
    cudaFuncSetAttribute(attn_kernel, cudaFuncAttributeMaxDynamicSharedMemorySize,
                         SM_TOTAL * sizeof(float));

    dim3 g(4, SPLITK);
    gemm_kernel<<<g, 256, GEMM_SMEM>>>(f1, f2, W1, W2);
    attn_kernel<<<256, 256, SM_TOTAL * sizeof(float)>>>(
        b1, b2, Aa, Av, Wa, Wv, Wca, Wcv, Wha, Whv, out);
}

// round 16
// speedup vs baseline: 1.1875x; 1.1456x over previous
#include <cuda_runtime.h>
#include <cuda_bf16.h>
#include <cuda_fp16.h>
#include <cstdint>

#define HW 327680          // 512*640 per image
#define KTOT 20480
#define KSTG 32            // K per pipeline stage
#define SPLITK 74          // uneven: first 48 blocks get 9 chunks, rest 8

#define ST 20              // smem words per 32-k fp16 row (16 data + 4 pad)
#define TILW (128 * ST)    // words per 128x32 fp16 tile = 2560
#define BUFW (2 * TILW)    // A + B per buffer = 5120 words
#define GEMM_SMEM (2 * BUFW * 4)   // 40960 bytes

typedef unsigned long long ull;

__device__ float g_part[SPLITK][512][128];   // split-K partials

__device__ __forceinline__ uint32_t cvt2h(float hi, float lo) {   // pack -> f16x2
    uint32_t r;
    asm("cvt.rn.f16x2.f32 %0, %1, %2;" : "=r"(r) : "f"(hi), "f"(lo));
    return r;
}
__device__ __forceinline__ void mma16816h(float* d, const uint32_t* a, const uint32_t* b) {
    asm volatile(
        "mma.sync.aligned.m16n8k16.row.col.f32.f16.f16.f32 "
        "{%0,%1,%2,%3}, {%4,%5,%6,%7}, {%8,%9}, {%0,%1,%2,%3};"
        : "+f"(d[0]), "+f"(d[1]), "+f"(d[2]), "+f"(d[3])
        : "r"(a[0]), "r"(a[1]), "r"(a[2]), "r"(a[3]), "r"(b[0]), "r"(b[1]));
}
__device__ __forceinline__ float tanha(float x) {
    float r;
    asm("tanh.approx.f32 %0, %1;" : "=f"(r) : "f"(x));
    return r;
}

// ====== Split-K fp16 single-term HMMA GEMM with fused stride-4 gather ======
// grid = (4 M-tiles of 128 rows, 74 K-splits), block = 256 (8 warps: 2m x 4n).
__global__ __launch_bounds__(256) void gemm_kernel(
    const float* __restrict__ f1, const float* __restrict__ f2,
    const float* __restrict__ W1, const float* __restrict__ W2)
{
    extern __shared__ __align__(16) uint32_t sm[];
    const int tid = threadIdx.x;
    const int mt = blockIdx.x;
    const int ky = blockIdx.y;
    const bool isVis = (mt == 3);
    const float* __restrict__ src = isVis ? f2 : f1;
    const float* __restrict__ Wm  = isVis ? W2 : W1;
    const int row0 = mt * 128;

    const int c0  = ky * 8 + min(ky, 48);
    const int NST = 8 + (ky < 48 ? 1 : 0);
    const int kc0 = c0 * KSTG;

    const int kp = tid & 15, rg = tid >> 4;
    const float* __restrict__ abase =
        src + (size_t)((isVis ? 0 : row0) + rg * 8) * HW;
    const int wn = tid >> 1, whalf = tid & 1;
    const float* __restrict__ wbase = Wm + (size_t)wn * KTOT + kc0;

    float a0[8], a1[8];
    float4 wv[4];

    auto loadStage = [&](int s) {
        int d0 = kc0 + s * KSTG + kp * 2;               // even; stays in one H-row
        unsigned hh = (unsigned)d0 / 160u;
        unsigned ww = (unsigned)d0 - hh * 160u;
        size_t off = (size_t)hh * 2560u + (size_t)ww * 4u;
#pragma unroll
        for (int j = 0; j < 8; ++j) {
            const float* p = abase + (size_t)j * HW + off;
            a0[j] = __ldg(p);
            a1[j] = __ldg(p + 4);
        }
        const float* wp = wbase + s * KSTG + whalf * 16;
#pragma unroll
        for (int q = 0; q < 4; ++q)
            wv[q] = *reinterpret_cast<const float4*>(wp + q * 4);
    };

    auto storeStage = [&](int buf) {
        uint32_t* Ab = sm + (size_t)buf * BUFW;
        uint32_t* Bb = Ab + TILW;
#pragma unroll
        for (int j = 0; j < 8; ++j) {
            int r = rg * 8 + j;
            Ab[r * ST + kp] = cvt2h(a1[j], a0[j]);
        }
#pragma unroll
        for (int q = 0; q < 4; ++q) {
            float4 v = wv[q];
            int w0 = wn * ST + whalf * 8 + 2 * q;
            *reinterpret_cast<uint2*>(Bb + w0) =
                make_uint2(cvt2h(v.y, v.x), cvt2h(v.w, v.z));
        }
    };

    const int wid = tid >> 5, lane = tid & 31;
    const int wm = wid >> 2, wnw = wid & 3;   // warp tile: rows wm*64, cols wnw*32
    const int l4 = lane >> 2, lm = lane & 3;

    float acc[4][4][4];
#pragma unroll
    for (int i = 0; i < 4; ++i)
#pragma unroll
        for (int j = 0; j < 4; ++j)
#pragma unroll
            for (int c = 0; c < 4; ++c) acc[i][j][c] = 0.0f;

    loadStage(0);
    storeStage(0);
    __syncthreads();

    for (int s = 0; s < NST; ++s) {
        int buf = s & 1;
        if (s + 1 < NST) loadStage(s + 1);

        const uint32_t* Ab = sm + (size_t)buf * BUFW;
        const uint32_t* Bb = Ab + TILW;

#pragma unroll
        for (int kb = 0; kb < 2; ++kb) {            // k-step of 16 = 8 words
            const int ko = kb * 8 + lm;
            uint32_t af[4][4], bf[4][2];
#pragma unroll
            for (int i = 0; i < 4; ++i) {
                const uint32_t* p = Ab + (wm * 64 + i * 16 + l4) * ST + ko;
                af[i][0] = p[0]; af[i][1] = p[8 * ST]; af[i][2] = p[4]; af[i][3] = p[8 * ST + 4];
            }
#pragma unroll
            for (int j = 0; j < 4; ++j) {
                const uint32_t* p = Bb + (wnw * 32 + j * 8 + l4) * ST + ko;
                bf[j][0] = p[0]; bf[j][1] = p[4];
            }
#pragma unroll
            for (int i = 0; i < 4; ++i)
#pragma unroll
                for (int j = 0; j < 4; ++j)
                    mma16816h(acc[i][j], af[i], bf[j]);
        }

        if (s + 1 < NST) storeStage(buf ^ 1);
        __syncthreads();
    }

    // epilogue: write 64x32 warp tile to g_part
#pragma unroll
    for (int i = 0; i < 4; ++i) {
        int rlo = row0 + wm * 64 + i * 16 + l4;
#pragma unroll
        for (int j = 0; j < 4; ++j) {
            int col = wnw * 32 + j * 8 + 2 * lm;
            *reinterpret_cast<float2*>(&g_part[blockIdx.y][rlo][col]) =
                make_float2(acc[i][j][0], acc[i][j][1]);
            *reinterpret_cast<float2*>(&g_part[blockIdx.y][rlo + 8][col]) =
                make_float2(acc[i][j][2], acc[i][j][3]);
        }
    }
}

// ===================== attn with fp16-HMMA phase 2 (unchanged) =====================
#define SM_ENC   0        // 384
#define SM_VIS   384      // 128
#define SM_XAV   512      // 768 (pre-scaled by 1/16)
#define SM_WH    1280     // 96
#define SM_WCE   1408     // 32 rows x 280 halves = 4480 words -> 5888
#define SM_ATT   5888     // 8 warps x 16 rows x 140 words = 17920 -> 23808
#define SM_TOTAL 23808    // words -> 95232 bytes
#define AST 280           // halves per strip row (272 data + 8 pad)
#define ASTW 140          // words per strip row

__global__ __launch_bounds__(256) void attn_kernel(
    const float* __restrict__ b1, const float* __restrict__ b2,
    const float* __restrict__ Aa, const float* __restrict__ Av,
    const float* __restrict__ Wa, const float* __restrict__ Wv,
    const float* __restrict__ Wca, const float* __restrict__ Wcv,
    const float* __restrict__ Wha, const float* __restrict__ Whv,
    float* __restrict__ out)
{
    extern __shared__ __align__(16) float fsm[];
    float* enc_a = fsm + SM_ENC;
    float* visr  = fsm + SM_VIS;
    float* XAv   = fsm + SM_XAV;
    float* Wh_s  = fsm + SM_WH;
    __half* wce  = reinterpret_cast<__half*>(fsm + SM_WCE);
    float4* red  = reinterpret_cast<float4*>(fsm + SM_ATT);   // alias before strips

    const int tid = threadIdx.x;
    const int b = blockIdx.x >> 1;
    const int mod = blockIdx.x & 1;   // 0 = audio, 1 = visual

    // split-K reduction: 4 rows x 128 cols over 74 partials
    {
        int e = tid & 127;
        int half = tid >> 7;
        int rl = e >> 5, q = e & 31;
        int grow = (rl < 3) ? (b * 3 + rl) : (384 + b);
        float4 a4 = make_float4(0.f, 0.f, 0.f, 0.f);
#pragma unroll 8
        for (int s = 0; s < 37; ++s) {
            const float4 v = *reinterpret_cast<const float4*>(
                &g_part[half * 37 + s][grow][q * 4]);
            a4.x += v.x; a4.y += v.y; a4.z += v.z; a4.w += v.w;
        }
        red[tid] = a4;
    }
    if (tid < 96) Wh_s[tid] = (mod ? Whv : Wha)[tid];
    // stage WcE (fp16): cols 0..255 = Wc, 256..258 = Wx, 259..271 = 0
    {
        const float* Wc = mod ? Wcv : Wca;
        for (int idx = tid; idx < 2048; idx += 256) {   // float4 granularity
            int h = idx >> 6, m4 = idx & 63;
            float4 v = *reinterpret_cast<const float4*>(Wc + h * 256 + m4 * 4);
            __half2* dst = reinterpret_cast<__half2*>(wce + h * AST + m4 * 4);
            dst[0] = __floats2half2_rn(v.x, v.y);
            dst[1] = __floats2half2_rn(v.z, v.w);
        }
        const float* Wx = mod ? Wv : Wa;
        if (tid < 96) {
            int h = tid / 3, c = tid - 3 * h;
            wce[h * AST + 256 + c] = __float2half_rn(Wx[tid]);
        }
        for (int idx = tid; idx < 32 * 13; idx += 256) {
            int h = idx / 13, c = idx - 13 * h;
            wce[h * AST + 259 + c] = __float2half_rn(0.0f);
        }
    }
    __syncthreads();

    if (tid < 128) {
        int rl = tid >> 5, q = tid & 31;
        float4 v0 = red[tid], v1 = red[128 + tid];
        float4 s4 = make_float4(v0.x + v1.x, v0.y + v1.y, v0.z + v1.z, v0.w + v1.w);
        if (rl < 3) {
            const float4 bb = *reinterpret_cast<const float4*>(&b1[q * 4]);
            *reinterpret_cast<float4*>(&enc_a[rl * 128 + q * 4]) =
                make_float4(s4.x + bb.x, s4.y + bb.y, s4.z + bb.z, s4.w + bb.w);
        } else {
            const float4 bb = *reinterpret_cast<const float4*>(&b2[q * 4]);
            *reinterpret_cast<float4*>(&visr[q * 4]) =
                make_float4(s4.x + bb.x, s4.y + bb.y, s4.z + bb.z, s4.w + bb.w);
        }
    }
    __syncthreads();

    const float* M = mod ? Av : Aa;
    {
        int m = tid;
        const float scale = 0.0625f;   // fold 1/sqrt(256) into XAv
        float av0 = (m < 128) ? enc_a[m]       : visr[m - 128];
        float av1 = (m < 128) ? enc_a[128 + m] : visr[m - 128];
        float av2 = (m < 128) ? enc_a[256 + m] : visr[m - 128];
        XAv[m]       = scale * (M[0] * av0 + M[1] * av1 + M[2] * av2);
        XAv[256 + m] = scale * (M[3] * av0 + M[4] * av1 + M[5] * av2);
        XAv[512 + m] = scale * (M[6] * av0 + M[7] * av1 + M[8] * av2);
    }
    __syncthreads();

    const int wid = tid >> 5, h = tid & 31;
    const int l4 = h >> 2, lm = h & 3;
    const int k0 = wid * 16;
    __half* strip = reinterpret_cast<__half*>(fsm + SM_ATT) + wid * 16 * AST;

    // ---- Phase 1: tanh rows (fp16) + e-columns ----
    float e0[16], e1[16], e2[16];
#pragma unroll
    for (int r = 0; r < 16; ++r) {
        int k = k0 + r;
        if (mod == 0) { e0[r] = enc_a[k]; e1[r] = enc_a[128 + k]; e2[r] = enc_a[256 + k]; }
        else          { e0[r] = visr[k];  e1[r] = e0[r];          e2[r] = e0[r]; }
    }
#pragma unroll
    for (int mc = 0; mc < 8; ++mc) {
        int m = mc * 32 + h;
        float x0 = XAv[m], x1 = XAv[256 + m], x2 = XAv[512 + m];
#pragma unroll
        for (int r = 0; r < 16; ++r) {
            float s = e0[r] * x0 + e1[r] * x1 + e2[r] * x2;
            strip[r * AST + m] = __float2half_rn(tanha(s));
        }
    }
    // e-columns 256..258 (lane h == r writes row r), zeros 259..271
#pragma unroll
    for (int r = 0; r < 16; ++r) {
        if (h == r) {
            strip[r * AST + 256] = __float2half_rn(e0[r]);
            strip[r * AST + 257] = __float2half_rn(e1[r]);
            strip[r * AST + 258] = __float2half_rn(e2[r]);
        }
    }
    for (int z = h; z < 16 * 13; z += 32) {
        int r = z / 13, c = z - 13 * r;
        strip[r * AST + 259 + c] = __float2half_rn(0.0f);
    }
    __syncwarp();

    // ---- Phase 2: H(16x32) = relu( strip(16x272) @ WcE^T(272x32) ) via fp16 HMMA
    const uint32_t* stripw = reinterpret_cast<const uint32_t*>(strip);
    const uint32_t* wcew   = reinterpret_cast<const uint32_t*>(wce);

    float acc[4][4];
#pragma unroll
    for (int j = 0; j < 4; ++j)
#pragma unroll
        for (int c = 0; c < 4; ++c) acc[j][c] = 0.0f;

#pragma unroll
    for (int t = 0; t < 17; ++t) {
        const int ko = t * 8 + lm;
        uint32_t a[4];
        const uint32_t* ap = stripw + l4 * ASTW + ko;
        a[0] = ap[0]; a[1] = ap[8 * ASTW]; a[2] = ap[4]; a[3] = ap[8 * ASTW + 4];
#pragma unroll
        for (int j = 0; j < 4; ++j) {
            const uint32_t* bp = wcew + (j * 8 + l4) * ASTW + ko;
            uint32_t bfr[2] = { bp[0], bp[4] };
            mma16816h(acc[j], a, bfr);
        }
    }

    // ---- Epilogue: relu, x Wh, reduce over h, + enc residual ----
    float r0lo = 0.f, r1lo = 0.f, r2lo = 0.f;
    float r0hi = 0.f, r1hi = 0.f, r2hi = 0.f;
#pragma unroll
    for (int j = 0; j < 4; ++j) {
        int h0 = j * 8 + 2 * lm, h1 = h0 + 1;
        float w00 = Wh_s[h0],      w01 = Wh_s[h1];
        float w10 = Wh_s[32 + h0], w11 = Wh_s[32 + h1];
        float w20 = Wh_s[64 + h0], w21 = Wh_s[64 + h1];
        float H00 = fmaxf(acc[j][0], 0.f), H01 = fmaxf(acc[j][1], 0.f);
        float H10 = fmaxf(acc[j][2], 0.f), H11 = fmaxf(acc[j][3], 0.f);
        r0lo += H00 * w00 + H01 * w01;
        r1lo += H00 * w10 + H01 * w11;
        r2lo += H00 * w20 + H01 * w21;
        r0hi += H10 * w00 + H11 * w01;
        r1hi += H10 * w10 + H11 * w11;
        r2hi += H10 * w20 + H11 * w21;
    }
#pragma unroll
    for (int o = 1; o <= 2; o <<= 1) {
        r0lo += __shfl_xor_sync(0xffffffffu, r0lo, o);
        r1lo += __shfl_xor_sync(0xffffffffu, r1lo, o);
        r2lo += __shfl_xor_sync(0xffffffffu, r2lo, o);
        r0hi += __shfl_xor_sync(0xffffffffu, r0hi, o);
        r1hi += __shfl_xor_sync(0xffffffffu, r1hi, o);
        r2hi += __shfl_xor_sync(0xffffffffu, r2hi, o);
    }
    if (lm == 0) {
        float* ob = out + (size_t)b * 768 + mod * 128;
        int klo = k0 + l4, khi = klo + 8;
        float a0, a1, a2, c0, c1, c2;
        if (mod == 0) {
            a0 = enc_a[klo]; a1 = enc_a[128 + klo]; a2 = enc_a[256 + klo];
            c0 = enc_a[khi]; c1 = enc_a[128 + khi]; c2 = enc_a[256 + khi];
        } else {
            a0 = visr[klo]; a1 = a0; a2 = a0;
            c0 = visr[khi]; c1 = c0; c2 = c0;
        }
        ob[klo]       = r0lo + a0;
        ob[256 + klo] = r1lo + a1;
        ob[512 + klo] = r2lo + a2;
        ob[khi]       = r0hi + c0;
        ob[256 + khi] = r1hi + c1;
        ob[512 + khi] = r2hi + c2;
    }
}

extern "C" void kernel_launch(void* const* d_in, const int* in_sizes, int n_in,
                              void* d_out, int out_size)
{
    const float* f1  = (const float*)d_in[0];
    const float* f2  = (const float*)d_in[1];
    const float* W1  = (const float*)d_in[2];
    const float* b1  = (const float*)d_in[3];
    const float* W2  = (const float*)d_in[4];
    const float* b2  = (const float*)d_in[5];
    const float* Aa  = (const float*)d_in[6];
    const float* Av  = (const float*)d_in[7];
    const float* Wa  = (const float*)d_in[8];
    const float* Wv  = (const float*)d_in[9];
    const float* Wca = (const float*)d_in[10];
    const float* Wcv = (const float*)d_in[11];
    const float* Wha = (const float*)d_in[12];
    const float* Whv = (const float*)d_in[13];
    float* out = (float*)d_out;

    cudaFuncSetAttribute(gemm_kernel, cudaFuncAttributeMaxDynamicSharedMemorySize,
                         GEMM_SMEM);
    cudaFuncSetAttribute(attn_kernel, cudaFuncAttributeMaxDynamicSharedMemorySize,
                         SM_TOTAL * sizeof(float));

    dim3 g(4, SPLITK);
    gemm_kernel<<<g, 256, GEMM_SMEM>>>(f1, f2, W1, W2);
    attn_kernel<<<256, 256, SM_TOTAL * sizeof(float)>>>(
        b1, b2, Aa, Av, Wa, Wv, Wca, Wcv, Wha, Whv, out);
}